// round 8
// baseline (speedup 1.0000x reference)
#include <cuda_runtime.h>
#include <cuda_fp16.h>
#include <cstdint>

#define Nn 2048
#define Mm 10
#define Dd 256
#define ROWS (Nn * Mm)      // 20480

// ---------------------------------------------------------------------------
// Scratch (device globals; no allocation allowed)
// ---------------------------------------------------------------------------
__device__ __align__(16) uint8_t g_A[(size_t)ROWS * Dd];  // normalized emb, e4m3
__device__ __align__(16) uint8_t g_B[(size_t)Nn * Dd];    // normalized centroids, e4m3
__device__ float g_rowsum[ROWS];
__device__ float g_pos[ROWS];   // stores t = |w|*(cos-1); shift cancels in lse-pos

__device__ __forceinline__ uint32_t smem_u32(const void* p) {
    uint32_t a;
    asm("{ .reg .u64 t; cvta.to.shared.u64 t, %1; cvt.u32.u64 %0, t; }" : "=r"(a) : "l"(p));
    return a;
}
__device__ __forceinline__ void cpa16(uint32_t dst, const void* src) {
    asm volatile("cp.async.cg.shared.global [%0], [%1], 16;" :: "r"(dst), "l"(src));
}
__device__ __forceinline__ void ldm_x4(uint32_t* r, uint32_t addr) {
    asm volatile("ldmatrix.sync.aligned.m8n8.x4.shared.b16 {%0,%1,%2,%3}, [%4];"
                 : "=r"(r[0]), "=r"(r[1]), "=r"(r[2]), "=r"(r[3]) : "r"(addr));
}
// e4m3 x e4m3 -> f32, K=32 per instruction
__device__ __forceinline__ void mma_fp8(float* c, const uint32_t* a,
                                        uint32_t b0, uint32_t b1) {
    asm volatile(
        "mma.sync.aligned.m16n8k32.row.col.f32.e4m3.e4m3.f32 "
        "{%0,%1,%2,%3}, {%4,%5,%6,%7}, {%8,%9}, {%0,%1,%2,%3};"
        : "+f"(c[0]), "+f"(c[1]), "+f"(c[2]), "+f"(c[3])
        : "r"(a[0]), "r"(a[1]), "r"(a[2]), "r"(a[3]), "r"(b0), "r"(b1));
}
// pack 4 floats -> 4 e4m3 bytes (byte0 = x0)
__device__ __forceinline__ uint32_t fp8x4(float x0, float x1, float x2, float x3) {
    uint16_t lo, hi;
    asm("cvt.rn.satfinite.e4m3x2.f32 %0, %1, %2;" : "=h"(lo) : "f"(x1), "f"(x0));
    asm("cvt.rn.satfinite.e4m3x2.f32 %0, %1, %2;" : "=h"(hi) : "f"(x3), "f"(x2));
    return (uint32_t)lo | ((uint32_t)hi << 16);
}

// ---------------------------------------------------------------------------
// Kernel 1: prep. One block per speaker n, 320 threads (warp m = utterance m).
// ---------------------------------------------------------------------------
__global__ void __launch_bounds__(320) prep_kernel(const float* __restrict__ emb) {
    const int n = blockIdx.x;
    const int tid = threadIdx.x;
    const int w = tid >> 5, lane = tid & 31;
    __shared__ float sv[Mm][Dd];
    __shared__ float cent[Dd];
    __shared__ float warp_red[8];
    __shared__ float cnorm;

    {   // per-utterance L2 normalize -> e4m3
        const float* src = emb + ((size_t)n * Mm + w) * Dd;
        float4 x0 = *(const float4*)(src + lane * 8);
        float4 x1 = *(const float4*)(src + lane * 8 + 4);
        float ss = x0.x * x0.x + x0.y * x0.y + x0.z * x0.z + x0.w * x0.w
                 + x1.x * x1.x + x1.y * x1.y + x1.z * x1.z + x1.w * x1.w;
#pragma unroll
        for (int off = 16; off > 0; off >>= 1) ss += __shfl_xor_sync(0xffffffffu, ss, off);
        float sc = 1.f / fmaxf(sqrtf(ss), 1e-12f);
        uint2 pk;
        pk.x = fp8x4(x0.x * sc, x0.y * sc, x0.z * sc, x0.w * sc);
        pk.y = fp8x4(x1.x * sc, x1.y * sc, x1.z * sc, x1.w * sc);
        *(uint2*)(g_A + (size_t)(n * Mm + w) * Dd + lane * 8) = pk;
        *(float4*)&sv[w][lane * 8] = x0;
        *(float4*)&sv[w][lane * 8 + 4] = x1;
    }
    __syncthreads();

    // centroid = l2norm(sum_m emb) (scale-invariant; skip /M)
    float s = 0.f;
    if (tid < Dd) {
#pragma unroll
        for (int m = 0; m < Mm; m++) s += sv[m][tid];
        float ss = s * s;
#pragma unroll
        for (int off = 16; off > 0; off >>= 1) ss += __shfl_xor_sync(0xffffffffu, ss, off);
        if (lane == 0) warp_red[tid >> 5] = ss;
    }
    __syncthreads();
    if (tid == 0) {
        float t = 0.f;
#pragma unroll
        for (int i = 0; i < 8; i++) t += warp_red[i];
        cnorm = fmaxf(sqrtf(t), 1e-12f);
    }
    __syncthreads();
    if (tid < Dd) cent[tid] = s / cnorm;
    if (tid < Mm) g_rowsum[n * Mm + tid] = 0.f;   // graph-replay-safe zeroing
    __syncthreads();
    if (tid < 32) {   // pack centroid -> e4m3, 8 per thread
        uint2 pk;
        pk.x = fp8x4(cent[tid * 8 + 0], cent[tid * 8 + 1], cent[tid * 8 + 2], cent[tid * 8 + 3]);
        pk.y = fp8x4(cent[tid * 8 + 4], cent[tid * 8 + 5], cent[tid * 8 + 6], cent[tid * 8 + 7]);
        *(uint2*)(g_B + (size_t)n * Dd + tid * 8) = pk;
    }
}

// ---------------------------------------------------------------------------
// Kernel 2: fp8 MMA GEMM (m16n8k32), CTA tile 128x128, warp tile 64x32
// (2x4 warps), BK=32 (one K-step/chunk), 3-stage cp.async pipeline.
// Static smem 36,864 B -> 2 CTAs/SM.
// Fused epilogue: t = |w|*(cos-1); rowsum += exp(t); pos = t.
// ---------------------------------------------------------------------------
#define BK 32
#define SROW 48                       // padded row stride, bytes (32 + 16)
#define NCHUNK (Dd / BK)              // 8
#define STG (128 * SROW)              // 6144 B per tile stage

__global__ void __launch_bounds__(256, 2)
gemm_lse_kernel(const float* __restrict__ wp, const float* __restrict__ bp) {
    __shared__ uint8_t smem[6 * STG]; // [A0 A1 A2 | B0 B1 B2]
    const uint32_t as0 = smem_u32(smem);
    const uint32_t bs0 = as0 + 3 * STG;

    const int tid = threadIdx.x;
    const int wid = tid >> 5, lane = tid & 31;
    const int wm = wid & 1;           // 0..1  (64-row slice)
    const int wn = wid >> 1;          // 0..3  (32-col slice)
    const int r0 = blockIdx.y * 128;
    const int c0 = blockIdx.x * 128;

    const int lrow = tid >> 1;        // 0..127
    const int lhalf = tid & 1;        // 16B half of 32B row-chunk

    auto load_chunk = [&](int c, int stg) {
        cpa16(as0 + stg * STG + lrow * SROW + lhalf * 16,
              g_A + (size_t)(r0 + lrow) * Dd + c * BK + lhalf * 16);
        cpa16(bs0 + stg * STG + lrow * SROW + lhalf * 16,
              g_B + (size_t)(c0 + lrow) * Dd + c * BK + lhalf * 16);
        asm volatile("cp.async.commit_group;" ::: "memory");
    };

    float acc[4][4][4] = {};

    load_chunk(0, 0);
    load_chunk(1, 1);

#pragma unroll
    for (int c = 0; c < NCHUNK; c++) {
        if (c <= 6) asm volatile("cp.async.wait_group 1;" ::: "memory");
        else        asm volatile("cp.async.wait_group 0;" ::: "memory");
        __syncthreads();
        if (c + 2 < NCHUNK) load_chunk(c + 2, (c + 2) % 3);

        const uint32_t ab = as0 + (c % 3) * STG;
        const uint32_t bb = bs0 + (c % 3) * STG;

        // A fragments: 4 tiles of 16 rows x 32B (full k32 operand each)
        uint32_t a[4][4];
#pragma unroll
        for (int mt = 0; mt < 4; mt++) {
            int row = wm * 64 + mt * 16 + (lane & 7) + ((lane >> 3) & 1) * 8;
            ldm_x4(a[mt], ab + row * SROW + (lane >> 4) * 16);
        }
        // B fragments: 2 x4 loads cover 4 n-groups of 8
        uint32_t b[2][4];
#pragma unroll
        for (int pr = 0; pr < 2; pr++) {
            int row = wn * 32 + pr * 16 + (lane & 7) + (lane >> 4) * 8;
            ldm_x4(b[pr], bb + row * SROW + ((lane >> 3) & 1) * 16);
        }
#pragma unroll
        for (int mt = 0; mt < 4; mt++)
#pragma unroll
            for (int nt = 0; nt < 4; nt++)
                mma_fp8(acc[mt][nt], a[mt],
                        b[nt >> 1][(nt & 1) * 2], b[nt >> 1][(nt & 1) * 2 + 1]);
    }

    // ---- fused epilogue: t = |w|*(cos-1); rowsum += exp(t); pos = t ----
    const float wabs = fabsf(*wp);
    const float nw = -wabs;
    const int q = lane >> 2, qi = lane & 3;
    const int cbase = c0 + wn * 32;

#pragma unroll
    for (int mt = 0; mt < 4; mt++) {
        const int rowA = r0 + wm * 64 + mt * 16 + q;
        const int rowB = rowA + 8;
        const int posA = rowA / Mm, posB = rowB / Mm;
        float sA = 0.f, sB = 0.f;
#pragma unroll
        for (int nt = 0; nt < 4; nt++) {
            const int col = cbase + nt * 8 + qi * 2;
            float t0 = fmaf(wabs, acc[mt][nt][0], nw);
            float t1 = fmaf(wabs, acc[mt][nt][1], nw);
            float t2 = fmaf(wabs, acc[mt][nt][2], nw);
            float t3 = fmaf(wabs, acc[mt][nt][3], nw);
            sA += __expf(t0) + __expf(t1);
            sB += __expf(t2) + __expf(t3);
            if (col == posA) g_pos[rowA] = t0;
            if (col + 1 == posA) g_pos[rowA] = t1;
            if (col == posB) g_pos[rowB] = t2;
            if (col + 1 == posB) g_pos[rowB] = t3;
        }
#pragma unroll
        for (int off = 2; off > 0; off >>= 1) {
            sA += __shfl_xor_sync(0xffffffffu, sA, off);
            sB += __shfl_xor_sync(0xffffffffu, sB, off);
        }
        if (qi == 0) {
            atomicAdd(&g_rowsum[rowA], sA);
            atomicAdd(&g_rowsum[rowB], sB);
        }
    }
}

// ---------------------------------------------------------------------------
// Kernel 3: loss = mean_r( log(rowsum[r]) - pos_t[r] )   (shift cancels)
// ---------------------------------------------------------------------------
__global__ void loss_kernel(float* __restrict__ out) {
    __shared__ float red[256];
    float s = 0.f;
    for (int r = threadIdx.x; r < ROWS; r += 256)
        s += __logf(g_rowsum[r]) - g_pos[r];
    red[threadIdx.x] = s;
    __syncthreads();
    for (int off = 128; off > 0; off >>= 1) {
        if (threadIdx.x < off) red[threadIdx.x] += red[threadIdx.x + off];
        __syncthreads();
    }
    if (threadIdx.x == 0) out[0] = red[0] / (float)ROWS;
}

// ---------------------------------------------------------------------------
extern "C" void kernel_launch(void* const* d_in, const int* in_sizes, int n_in,
                              void* d_out, int out_size) {
    const float* emb = (const float*)d_in[0];
    const float* w   = (const float*)d_in[1];
    const float* b   = (const float*)d_in[2];
    (void)b;
    float* out = (float*)d_out;

    prep_kernel<<<Nn, 320>>>(emb);
    gemm_lse_kernel<<<dim3(Nn / 128, ROWS / 128), 256>>>(w, b);
    loss_kernel<<<1, 256>>>(out);
}

// round 9
// speedup vs baseline: 1.2558x; 1.2558x over previous
#include <cuda_runtime.h>
#include <cuda_fp16.h>
#include <cstdint>

#define Nn 2048
#define Mm 10
#define Dd 256
#define ROWS (Nn * Mm)      // 20480

// ---------------------------------------------------------------------------
// Scratch (device globals; no allocation allowed)
// ---------------------------------------------------------------------------
__device__ __align__(16) __half g_A[(size_t)ROWS * Dd];  // normalized emb, fp16
__device__ __align__(16) __half g_B[(size_t)Nn * Dd];    // normalized centroids, fp16
__device__ float g_rowsum[ROWS];
__device__ float g_pos[ROWS];   // stores t = |w|*(cos-1); shift cancels in lse-pos

__device__ __forceinline__ uint32_t smem_u32(const void* p) {
    uint32_t a;
    asm("{ .reg .u64 t; cvta.to.shared.u64 t, %1; cvt.u32.u64 %0, t; }" : "=r"(a) : "l"(p));
    return a;
}
__device__ __forceinline__ void cpa16(uint32_t dst, const void* src) {
    asm volatile("cp.async.cg.shared.global [%0], [%1], 16;" :: "r"(dst), "l"(src));
}
__device__ __forceinline__ void ldm_x4(uint32_t* r, uint32_t addr) {
    asm volatile("ldmatrix.sync.aligned.m8n8.x4.shared.b16 {%0,%1,%2,%3}, [%4];"
                 : "=r"(r[0]), "=r"(r[1]), "=r"(r[2]), "=r"(r[3]) : "r"(addr));
}
// fp16 inputs, fp16 accumulator (2 packed .f16x2 regs)
__device__ __forceinline__ void mma_f16acc(uint32_t* c, const uint32_t* a,
                                           uint32_t b0, uint32_t b1) {
    asm volatile(
        "mma.sync.aligned.m16n8k16.row.col.f16.f16.f16.f16 "
        "{%0,%1}, {%2,%3,%4,%5}, {%6,%7}, {%0,%1};"
        : "+r"(c[0]), "+r"(c[1])
        : "r"(a[0]), "r"(a[1]), "r"(a[2]), "r"(a[3]), "r"(b0), "r"(b1));
}

// ---------------------------------------------------------------------------
// Kernel 1: prep. One block per speaker n, 320 threads (warp m = utterance m).
// ---------------------------------------------------------------------------
__global__ void __launch_bounds__(320) prep_kernel(const float* __restrict__ emb) {
    const int n = blockIdx.x;
    const int tid = threadIdx.x;
    const int w = tid >> 5, lane = tid & 31;
    __shared__ float sv[Mm][Dd];
    __shared__ float warp_red[8];
    __shared__ float cnorm;

    {   // per-utterance L2 normalize -> fp16
        const float* src = emb + ((size_t)n * Mm + w) * Dd;
        float4 x0 = *(const float4*)(src + lane * 8);
        float4 x1 = *(const float4*)(src + lane * 8 + 4);
        float ss = x0.x * x0.x + x0.y * x0.y + x0.z * x0.z + x0.w * x0.w
                 + x1.x * x1.x + x1.y * x1.y + x1.z * x1.z + x1.w * x1.w;
#pragma unroll
        for (int off = 16; off > 0; off >>= 1) ss += __shfl_xor_sync(0xffffffffu, ss, off);
        float sc = 1.f / fmaxf(sqrtf(ss), 1e-12f);
        __half2 p0 = __floats2half2_rn(x0.x * sc, x0.y * sc);
        __half2 p1 = __floats2half2_rn(x0.z * sc, x0.w * sc);
        __half2 p2 = __floats2half2_rn(x1.x * sc, x1.y * sc);
        __half2 p3 = __floats2half2_rn(x1.z * sc, x1.w * sc);
        uint4 v{*(uint32_t*)&p0, *(uint32_t*)&p1, *(uint32_t*)&p2, *(uint32_t*)&p3};
        *(uint4*)(g_A + (size_t)(n * Mm + w) * Dd + lane * 8) = v;
        *(float4*)&sv[w][lane * 8] = x0;
        *(float4*)&sv[w][lane * 8 + 4] = x1;
    }
    __syncthreads();

    // centroid = l2norm(sum_m emb) (scale-invariant; skip /M)
    float s = 0.f;
    if (tid < Dd) {
#pragma unroll
        for (int m = 0; m < Mm; m++) s += sv[m][tid];
        float ss = s * s;
#pragma unroll
        for (int off = 16; off > 0; off >>= 1) ss += __shfl_xor_sync(0xffffffffu, ss, off);
        if (lane == 0) warp_red[tid >> 5] = ss;
    }
    __syncthreads();
    if (tid == 0) {
        float t = 0.f;
#pragma unroll
        for (int i = 0; i < 8; i++) t += warp_red[i];
        cnorm = fmaxf(sqrtf(t), 1e-12f);
    }
    __syncthreads();
    if (tid < Dd) g_B[(size_t)n * Dd + tid] = __float2half(s / cnorm);
    if (tid < Mm) g_rowsum[n * Mm + tid] = 0.f;   // graph-replay-safe zeroing
}

// ---------------------------------------------------------------------------
// Kernel 2: fp16 HMMA (fp16 acc), CTA tile 128x256, warp tile 64x64 (2x4),
// BK=32, 3-stage cp.async pipeline, one __syncthreads per chunk.
// MMA:LDSM ratio 4:1 (smem-BW relief) AND 2 CTAs/SM (16 warps, latency cover).
// Fused epilogue: t = |w|*(cos-1); rowsum += exp(t); pos = t.
// ---------------------------------------------------------------------------
#define BK 32
#define SSTR 40                       // padded row stride (elems); 80B
#define NCHUNK (Dd / BK)              // 8
#define STGA (128 * SSTR * 2)         // 10240 B per A stage
#define STGB (256 * SSTR * 2)         // 20480 B per B stage
#define SMEM_BYTES (3 * (STGA + STGB))  // 92160

__global__ void __launch_bounds__(256, 2)
gemm_lse_kernel(const float* __restrict__ wp, const float* __restrict__ bp) {
    extern __shared__ char smem[];
    const uint32_t as0 = smem_u32(smem);
    const uint32_t bs0 = as0 + 3 * STGA;

    const int tid = threadIdx.x;
    const int wid = tid >> 5, lane = tid & 31;
    const int wm = wid >> 2;          // 0..1  (64-row slice)
    const int wn = wid & 3;           // 0..3  (64-col slice)
    const int r0 = blockIdx.y * 128;
    const int c0 = blockIdx.x * 256;

    const int lrow = tid >> 2;        // 0..63
    const int lquad = tid & 3;        // 16B quad within 64B of row-chunk

    auto load_chunk = [&](int c, int stg) {
#pragma unroll
        for (int i = 0; i < 2; i++) {
            int row = lrow + i * 64;
            cpa16(as0 + stg * STGA + row * (SSTR * 2) + lquad * 16,
                  g_A + (size_t)(r0 + row) * Dd + c * BK + lquad * 8);
        }
#pragma unroll
        for (int i = 0; i < 4; i++) {
            int row = lrow + i * 64;
            cpa16(bs0 + stg * STGB + row * (SSTR * 2) + lquad * 16,
                  g_B + (size_t)(c0 + row) * Dd + c * BK + lquad * 8);
        }
        asm volatile("cp.async.commit_group;" ::: "memory");
    };

    uint32_t acc[4][8][2] = {};       // fp16x2 accumulators

    load_chunk(0, 0);
    load_chunk(1, 1);

#pragma unroll
    for (int c = 0; c < NCHUNK; c++) {
        if (c <= 6) asm volatile("cp.async.wait_group 1;" ::: "memory");
        else        asm volatile("cp.async.wait_group 0;" ::: "memory");
        __syncthreads();
        if (c + 2 < NCHUNK) load_chunk(c + 2, (c + 2) % 3);

        const uint32_t ab = as0 + (c % 3) * STGA;
        const uint32_t bb = bs0 + (c % 3) * STGB;
#pragma unroll
        for (int ks = 0; ks < 2; ks++) {
            const int k0 = ks * 16;
            uint32_t a[4][4];
#pragma unroll
            for (int mt = 0; mt < 4; mt++) {
                int row = wm * 64 + mt * 16 + (lane & 15);
                int col = k0 + (lane >> 4) * 8;
                ldm_x4(a[mt], ab + row * (SSTR * 2) + col * 2);
            }
            uint32_t b[4][4];
#pragma unroll
            for (int ng = 0; ng < 4; ng++) {
                int row = wn * 64 + ng * 16 + (lane & 7) + (lane >> 4) * 8;
                int col = k0 + ((lane >> 3) & 1) * 8;
                ldm_x4(b[ng], bb + row * (SSTR * 2) + col * 2);
            }
#pragma unroll
            for (int mt = 0; mt < 4; mt++)
#pragma unroll
                for (int nt = 0; nt < 8; nt++)
                    mma_f16acc(acc[mt][nt], a[mt],
                               b[nt >> 1][(nt & 1) * 2], b[nt >> 1][(nt & 1) * 2 + 1]);
        }
    }

    // ---- fused epilogue: t = |w|*(cos-1); rowsum += exp(t); pos = t ----
    const float wabs = fabsf(*wp);
    const float nw = -wabs;
    const int q = lane >> 2, qi = lane & 3;
    const int cbase = c0 + wn * 64;

#pragma unroll
    for (int mt = 0; mt < 4; mt++) {
        const int rowA = r0 + wm * 64 + mt * 16 + q;
        const int rowB = rowA + 8;
        const int posA = rowA / Mm, posB = rowB / Mm;
        float sA = 0.f, sB = 0.f;
#pragma unroll
        for (int nt = 0; nt < 8; nt++) {
            const int col = cbase + nt * 8 + qi * 2;
            float2 vA = __half22float2(*(__half2*)&acc[mt][nt][0]);
            float2 vB = __half22float2(*(__half2*)&acc[mt][nt][1]);
            float t0 = fmaf(wabs, vA.x, nw);
            float t1 = fmaf(wabs, vA.y, nw);
            float t2 = fmaf(wabs, vB.x, nw);
            float t3 = fmaf(wabs, vB.y, nw);
            sA += __expf(t0) + __expf(t1);
            sB += __expf(t2) + __expf(t3);
            if (col == posA) g_pos[rowA] = t0;
            if (col + 1 == posA) g_pos[rowA] = t1;
            if (col == posB) g_pos[rowB] = t2;
            if (col + 1 == posB) g_pos[rowB] = t3;
        }
#pragma unroll
        for (int off = 2; off > 0; off >>= 1) {
            sA += __shfl_xor_sync(0xffffffffu, sA, off);
            sB += __shfl_xor_sync(0xffffffffu, sB, off);
        }
        if (qi == 0) {
            atomicAdd(&g_rowsum[rowA], sA);
            atomicAdd(&g_rowsum[rowB], sB);
        }
    }
}

// ---------------------------------------------------------------------------
// Kernel 3: loss = mean_r( log(rowsum[r]) - pos_t[r] ), 1024 thr, vectorized.
// ---------------------------------------------------------------------------
__global__ void __launch_bounds__(1024) loss_kernel(float* __restrict__ out) {
    __shared__ float red[32];
    const int tid = threadIdx.x;
    float s = 0.f;
#pragma unroll
    for (int i = 0; i < ROWS / 4096; i++) {
        int r4 = tid + i * 1024;
        float4 rs = *(const float4*)&g_rowsum[r4 * 4];
        float4 ps = *(const float4*)&g_pos[r4 * 4];
        s += __logf(rs.x) - ps.x + __logf(rs.y) - ps.y
           + __logf(rs.z) - ps.z + __logf(rs.w) - ps.w;
    }
#pragma unroll
    for (int off = 16; off > 0; off >>= 1) s += __shfl_xor_sync(0xffffffffu, s, off);
    if ((tid & 31) == 0) red[tid >> 5] = s;
    __syncthreads();
    if (tid < 32) {
        float t = red[tid];
#pragma unroll
        for (int off = 16; off > 0; off >>= 1) t += __shfl_xor_sync(0xffffffffu, t, off);
        if (tid == 0) out[0] = t / (float)ROWS;
    }
}

// ---------------------------------------------------------------------------
extern "C" void kernel_launch(void* const* d_in, const int* in_sizes, int n_in,
                              void* d_out, int out_size) {
    const float* emb = (const float*)d_in[0];
    const float* w   = (const float*)d_in[1];
    const float* b   = (const float*)d_in[2];
    (void)b;
    float* out = (float*)d_out;

    static int smem_set = 0;
    if (!smem_set) {
        cudaFuncSetAttribute(gemm_lse_kernel,
                             cudaFuncAttributeMaxDynamicSharedMemorySize, SMEM_BYTES);
        smem_set = 1;
    }

    prep_kernel<<<Nn, 320>>>(emb);
    gemm_lse_kernel<<<dim3(Nn / 256, ROWS / 128), 256, SMEM_BYTES>>>(w, b);
    loss_kernel<<<1, 1024>>>(out);
}

// round 10
// speedup vs baseline: 1.3068x; 1.0406x over previous
#include <cuda_runtime.h>
#include <cuda_fp16.h>
#include <cstdint>

#define Nn 2048
#define Mm 10
#define Dd 256
#define ROWS (Nn * Mm)      // 20480

// ---------------------------------------------------------------------------
// Scratch (device globals; no allocation allowed)
// ---------------------------------------------------------------------------
__device__ __align__(16) __half g_A[(size_t)ROWS * Dd];  // normalized emb, fp16
__device__ __align__(16) __half g_B[(size_t)Nn * Dd];    // normalized centroids, fp16
__device__ float g_rowsum[ROWS];
__device__ float g_pos[ROWS];   // stores t = |w|*(cos-1); shift cancels in lse-pos

__device__ __forceinline__ uint32_t smem_u32(const void* p) {
    uint32_t a;
    asm("{ .reg .u64 t; cvta.to.shared.u64 t, %1; cvt.u32.u64 %0, t; }" : "=r"(a) : "l"(p));
    return a;
}
__device__ __forceinline__ void cpa16(uint32_t dst, const void* src) {
    asm volatile("cp.async.cg.shared.global [%0], [%1], 16;" :: "r"(dst), "l"(src));
}
__device__ __forceinline__ void ldm_x4(uint32_t* r, uint32_t addr) {
    asm volatile("ldmatrix.sync.aligned.m8n8.x4.shared.b16 {%0,%1,%2,%3}, [%4];"
                 : "=r"(r[0]), "=r"(r[1]), "=r"(r[2]), "=r"(r[3]) : "r"(addr));
}
// fp16 inputs, fp16 accumulator (2 packed .f16x2 regs)
__device__ __forceinline__ void mma_f16acc(uint32_t* c, const uint32_t* a,
                                           uint32_t b0, uint32_t b1) {
    asm volatile(
        "mma.sync.aligned.m16n8k16.row.col.f16.f16.f16.f16 "
        "{%0,%1}, {%2,%3,%4,%5}, {%6,%7}, {%0,%1};"
        : "+r"(c[0]), "+r"(c[1])
        : "r"(a[0]), "r"(a[1]), "r"(a[2]), "r"(a[3]), "r"(b0), "r"(b1));
}

// ---------------------------------------------------------------------------
// Kernel 1: prep. One block per speaker n, 320 threads (warp m = utterance m).
// Also computes g_pos[n*Mm+m] = |w|*(cos(emb_nm, cent_n) - 1) in fp32 so the
// GEMM epilogue needs no diagonal handling at all.
// ---------------------------------------------------------------------------
__global__ void __launch_bounds__(320) prep_kernel(const float* __restrict__ emb,
                                                   const float* __restrict__ wp) {
    const int n = blockIdx.x;
    const int tid = threadIdx.x;
    const int w = tid >> 5, lane = tid & 31;
    __shared__ float sv[Mm][Dd];
    __shared__ float cent[Dd];
    __shared__ float warp_red[8];
    __shared__ float cnorm;

    float4 x0, x1;
    float sc;
    {   // per-utterance L2 normalize -> fp16
        const float* src = emb + ((size_t)n * Mm + w) * Dd;
        x0 = *(const float4*)(src + lane * 8);
        x1 = *(const float4*)(src + lane * 8 + 4);
        float ss = x0.x * x0.x + x0.y * x0.y + x0.z * x0.z + x0.w * x0.w
                 + x1.x * x1.x + x1.y * x1.y + x1.z * x1.z + x1.w * x1.w;
#pragma unroll
        for (int off = 16; off > 0; off >>= 1) ss += __shfl_xor_sync(0xffffffffu, ss, off);
        sc = 1.f / fmaxf(sqrtf(ss), 1e-12f);
        __half2 p0 = __floats2half2_rn(x0.x * sc, x0.y * sc);
        __half2 p1 = __floats2half2_rn(x0.z * sc, x0.w * sc);
        __half2 p2 = __floats2half2_rn(x1.x * sc, x1.y * sc);
        __half2 p3 = __floats2half2_rn(x1.z * sc, x1.w * sc);
        uint4 v{*(uint32_t*)&p0, *(uint32_t*)&p1, *(uint32_t*)&p2, *(uint32_t*)&p3};
        *(uint4*)(g_A + (size_t)(n * Mm + w) * Dd + lane * 8) = v;
        *(float4*)&sv[w][lane * 8] = x0;
        *(float4*)&sv[w][lane * 8 + 4] = x1;
    }
    __syncthreads();

    // centroid = l2norm(sum_m emb) (scale-invariant; skip /M)
    float s = 0.f;
    if (tid < Dd) {
#pragma unroll
        for (int m = 0; m < Mm; m++) s += sv[m][tid];
        float ss = s * s;
#pragma unroll
        for (int off = 16; off > 0; off >>= 1) ss += __shfl_xor_sync(0xffffffffu, ss, off);
        if (lane == 0) warp_red[tid >> 5] = ss;
    }
    __syncthreads();
    if (tid == 0) {
        float t = 0.f;
#pragma unroll
        for (int i = 0; i < 8; i++) t += warp_red[i];
        cnorm = fmaxf(sqrtf(t), 1e-12f);
    }
    __syncthreads();
    if (tid < Dd) {
        float cv = s / cnorm;
        cent[tid] = cv;
        g_B[(size_t)n * Dd + tid] = __float2half(cv);
    }
    if (tid < Mm) g_rowsum[n * Mm + tid] = 0.f;   // graph-replay-safe zeroing
    __syncthreads();

    // pos: warp w computes dot(raw row, cent) * sc in fp32
    {
        const float* cp = cent + lane * 8;
        float d = x0.x * cp[0] + x0.y * cp[1] + x0.z * cp[2] + x0.w * cp[3]
                + x1.x * cp[4] + x1.y * cp[5] + x1.z * cp[6] + x1.w * cp[7];
#pragma unroll
        for (int off = 16; off > 0; off >>= 1) d += __shfl_xor_sync(0xffffffffu, d, off);
        if (lane == 0) {
            float wabs = fabsf(*wp);
            g_pos[n * Mm + w] = wabs * (d * sc - 1.f);
        }
    }
}

// ---------------------------------------------------------------------------
// Kernel 2: fp16 HMMA (fp16 acc), CTA tile 128x256, warp tile 64x64 (2x4),
// BK=32, 3-stage cp.async pipeline, one __syncthreads per chunk.
// Fused epilogue (branch-free): t = |w|*(cos-1); rowsum += exp(t).
// ---------------------------------------------------------------------------
#define BK 32
#define SSTR 40                       // padded row stride (elems); 80B
#define NCHUNK (Dd / BK)              // 8
#define STGA (128 * SSTR * 2)         // 10240 B per A stage
#define STGB (256 * SSTR * 2)         // 20480 B per B stage
#define SMEM_BYTES (3 * (STGA + STGB))  // 92160

__global__ void __launch_bounds__(256, 2)
gemm_lse_kernel(const float* __restrict__ wp) {
    extern __shared__ char smem[];
    const uint32_t as0 = smem_u32(smem);
    const uint32_t bs0 = as0 + 3 * STGA;

    const int tid = threadIdx.x;
    const int wid = tid >> 5, lane = tid & 31;
    const int wm = wid >> 2;          // 0..1  (64-row slice)
    const int wn = wid & 3;           // 0..3  (64-col slice)
    const int r0 = blockIdx.y * 128;
    const int c0 = blockIdx.x * 256;

    const int lrow = tid >> 2;        // 0..63
    const int lquad = tid & 3;        // 16B quad within 64B of row-chunk

    auto load_chunk = [&](int c, int stg) {
#pragma unroll
        for (int i = 0; i < 2; i++) {
            int row = lrow + i * 64;
            cpa16(as0 + stg * STGA + row * (SSTR * 2) + lquad * 16,
                  g_A + (size_t)(r0 + row) * Dd + c * BK + lquad * 8);
        }
#pragma unroll
        for (int i = 0; i < 4; i++) {
            int row = lrow + i * 64;
            cpa16(bs0 + stg * STGB + row * (SSTR * 2) + lquad * 16,
                  g_B + (size_t)(c0 + row) * Dd + c * BK + lquad * 8);
        }
        asm volatile("cp.async.commit_group;" ::: "memory");
    };

    uint32_t acc[4][8][2] = {};       // fp16x2 accumulators

    load_chunk(0, 0);
    load_chunk(1, 1);

#pragma unroll
    for (int c = 0; c < NCHUNK; c++) {
        if (c <= 6) asm volatile("cp.async.wait_group 1;" ::: "memory");
        else        asm volatile("cp.async.wait_group 0;" ::: "memory");
        __syncthreads();
        if (c + 2 < NCHUNK) load_chunk(c + 2, (c + 2) % 3);

        const uint32_t ab = as0 + (c % 3) * STGA;
        const uint32_t bb = bs0 + (c % 3) * STGB;
#pragma unroll
        for (int ks = 0; ks < 2; ks++) {
            const int k0 = ks * 16;
            uint32_t a[4][4];
#pragma unroll
            for (int mt = 0; mt < 4; mt++) {
                int row = wm * 64 + mt * 16 + (lane & 15);
                int col = k0 + (lane >> 4) * 8;
                ldm_x4(a[mt], ab + row * (SSTR * 2) + col * 2);
            }
            uint32_t b[4][4];
#pragma unroll
            for (int ng = 0; ng < 4; ng++) {
                int row = wn * 64 + ng * 16 + (lane & 7) + (lane >> 4) * 8;
                int col = k0 + ((lane >> 3) & 1) * 8;
                ldm_x4(b[ng], bb + row * (SSTR * 2) + col * 2);
            }
#pragma unroll
            for (int mt = 0; mt < 4; mt++)
#pragma unroll
                for (int nt = 0; nt < 8; nt++)
                    mma_f16acc(acc[mt][nt], a[mt],
                               b[nt >> 1][(nt & 1) * 2], b[nt >> 1][(nt & 1) * 2 + 1]);
        }
    }

    // ---- fused epilogue (branch-free): rowsum += exp(|w|*(cos-1)) ----
    const float wabs = fabsf(*wp);
    const float nw = -wabs;
    const int q = lane >> 2, qi = lane & 3;

#pragma unroll
    for (int mt = 0; mt < 4; mt++) {
        const int rowA = r0 + wm * 64 + mt * 16 + q;
        const int rowB = rowA + 8;
        float sA = 0.f, sB = 0.f;
#pragma unroll
        for (int nt = 0; nt < 8; nt++) {
            float2 vA = __half22float2(*(__half2*)&acc[mt][nt][0]);
            float2 vB = __half22float2(*(__half2*)&acc[mt][nt][1]);
            sA += __expf(fmaf(wabs, vA.x, nw)) + __expf(fmaf(wabs, vA.y, nw));
            sB += __expf(fmaf(wabs, vB.x, nw)) + __expf(fmaf(wabs, vB.y, nw));
        }
#pragma unroll
        for (int off = 2; off > 0; off >>= 1) {
            sA += __shfl_xor_sync(0xffffffffu, sA, off);
            sB += __shfl_xor_sync(0xffffffffu, sB, off);
        }
        if (qi == 0) {
            atomicAdd(&g_rowsum[rowA], sA);
            atomicAdd(&g_rowsum[rowB], sB);
        }
    }
}

// ---------------------------------------------------------------------------
// Kernel 3: loss = mean_r( log(rowsum[r]) - pos_t[r] ), 1024 thr, vectorized.
// ---------------------------------------------------------------------------
__global__ void __launch_bounds__(1024) loss_kernel(float* __restrict__ out) {
    __shared__ float red[32];
    const int tid = threadIdx.x;
    float s = 0.f;
#pragma unroll
    for (int i = 0; i < ROWS / 4096; i++) {
        int r4 = tid + i * 1024;
        float4 rs = *(const float4*)&g_rowsum[r4 * 4];
        float4 ps = *(const float4*)&g_pos[r4 * 4];
        s += __logf(rs.x) - ps.x + __logf(rs.y) - ps.y
           + __logf(rs.z) - ps.z + __logf(rs.w) - ps.w;
    }
#pragma unroll
    for (int off = 16; off > 0; off >>= 1) s += __shfl_xor_sync(0xffffffffu, s, off);
    if ((tid & 31) == 0) red[tid >> 5] = s;
    __syncthreads();
    if (tid < 32) {
        float t = red[tid];
#pragma unroll
        for (int off = 16; off > 0; off >>= 1) t += __shfl_xor_sync(0xffffffffu, t, off);
        if (tid == 0) out[0] = t / (float)ROWS;
    }
}

// ---------------------------------------------------------------------------
extern "C" void kernel_launch(void* const* d_in, const int* in_sizes, int n_in,
                              void* d_out, int out_size) {
    const float* emb = (const float*)d_in[0];
    const float* w   = (const float*)d_in[1];
    const float* b   = (const float*)d_in[2];
    (void)b;
    float* out = (float*)d_out;

    static int smem_set = 0;
    if (!smem_set) {
        cudaFuncSetAttribute(gemm_lse_kernel,
                             cudaFuncAttributeMaxDynamicSharedMemorySize, SMEM_BYTES);
        smem_set = 1;
    }

    prep_kernel<<<Nn, 320>>>(emb, w);
    gemm_lse_kernel<<<dim3(Nn / 256, ROWS / 128), 256, SMEM_BYTES>>>(w);
    loss_kernel<<<1, 1024>>>(out);
}

// round 11
// speedup vs baseline: 1.3603x; 1.0409x over previous
#include <cuda_runtime.h>
#include <cuda_fp16.h>
#include <cstdint>

#define Nn 2048
#define Mm 10
#define Dd 256
#define ROWS (Nn * Mm)      // 20480

// ---------------------------------------------------------------------------
// Scratch (device globals; no allocation allowed)
// ---------------------------------------------------------------------------
__device__ __align__(16) __half g_A[(size_t)ROWS * Dd];  // normalized emb, fp16
__device__ __align__(16) __half g_B[(size_t)Nn * Dd];    // normalized centroids, fp16
__device__ float g_rowsum[ROWS];
__device__ float g_pos[ROWS];   // stores t = |w|*(cos-1); shift cancels in lse-pos

__device__ __forceinline__ uint32_t smem_u32(const void* p) {
    uint32_t a;
    asm("{ .reg .u64 t; cvta.to.shared.u64 t, %1; cvt.u32.u64 %0, t; }" : "=r"(a) : "l"(p));
    return a;
}
__device__ __forceinline__ void cpa16(uint32_t dst, const void* src) {
    asm volatile("cp.async.cg.shared.global [%0], [%1], 16;" :: "r"(dst), "l"(src));
}
__device__ __forceinline__ void ldm_x4(uint32_t* r, uint32_t addr) {
    asm volatile("ldmatrix.sync.aligned.m8n8.x4.shared.b16 {%0,%1,%2,%3}, [%4];"
                 : "=r"(r[0]), "=r"(r[1]), "=r"(r[2]), "=r"(r[3]) : "r"(addr));
}
__device__ __forceinline__ void mma_f16acc(uint32_t* c, const uint32_t* a,
                                           uint32_t b0, uint32_t b1) {
    asm volatile(
        "mma.sync.aligned.m16n8k16.row.col.f16.f16.f16.f16 "
        "{%0,%1}, {%2,%3,%4,%5}, {%6,%7}, {%0,%1};"
        : "+r"(c[0]), "+r"(c[1])
        : "r"(a[0]), "r"(a[1]), "r"(a[2]), "r"(a[3]), "r"(b0), "r"(b1));
}
#define GBAR(id) asm volatile("bar.sync %0, 320;" :: "r"(id) : "memory")

// ---------------------------------------------------------------------------
// Kernel 1: prep. 2 speakers per block (640 thr), named barriers per group
// so the two speakers' dependency chains interleave. Computes fp16 A/B and
// fp32-exact pos = |w|*(cos-1); zeroes rowsum.
// ---------------------------------------------------------------------------
__global__ void __launch_bounds__(640) prep_kernel(const float* __restrict__ emb,
                                                   const float* __restrict__ wp) {
    const int tid = threadIdx.x;
    const int gid = tid / 320;          // speaker group 0/1
    const int t = tid % 320;
    const int n = blockIdx.x * 2 + gid;
    const int w = t >> 5, lane = t & 31;
    const int bar = gid + 1;
    __shared__ float sv[2][Mm][Dd];
    __shared__ float cent[2][Dd];
    __shared__ float wred[2][8];

    float4 x0, x1;
    float sc;
    {   // per-utterance L2 normalize -> fp16 (warp w = utterance w)
        const float* src = emb + ((size_t)n * Mm + w) * Dd;
        x0 = *(const float4*)(src + lane * 8);
        x1 = *(const float4*)(src + lane * 8 + 4);
        float ss = x0.x * x0.x + x0.y * x0.y + x0.z * x0.z + x0.w * x0.w
                 + x1.x * x1.x + x1.y * x1.y + x1.z * x1.z + x1.w * x1.w;
#pragma unroll
        for (int off = 16; off > 0; off >>= 1) ss += __shfl_xor_sync(0xffffffffu, ss, off);
        sc = 1.f / fmaxf(sqrtf(ss), 1e-12f);
        __half2 p0 = __floats2half2_rn(x0.x * sc, x0.y * sc);
        __half2 p1 = __floats2half2_rn(x0.z * sc, x0.w * sc);
        __half2 p2 = __floats2half2_rn(x1.x * sc, x1.y * sc);
        __half2 p3 = __floats2half2_rn(x1.z * sc, x1.w * sc);
        uint4 v{*(uint32_t*)&p0, *(uint32_t*)&p1, *(uint32_t*)&p2, *(uint32_t*)&p3};
        *(uint4*)(g_A + (size_t)(n * Mm + w) * Dd + lane * 8) = v;
        *(float4*)&sv[gid][w][lane * 8] = x0;
        *(float4*)&sv[gid][w][lane * 8 + 4] = x1;
    }
    GBAR(bar);

    float s = 0.f;
    if (t < Dd) {
#pragma unroll
        for (int m = 0; m < Mm; m++) s += sv[gid][m][t];
        float ss = s * s;
#pragma unroll
        for (int off = 16; off > 0; off >>= 1) ss += __shfl_xor_sync(0xffffffffu, ss, off);
        if (lane == 0) wred[gid][t >> 5] = ss;
    }
    GBAR(bar);

    // replicated final reduce (no extra sync)
    float tot = wred[gid][0] + wred[gid][1] + wred[gid][2] + wred[gid][3]
              + wred[gid][4] + wred[gid][5] + wred[gid][6] + wred[gid][7];
    float cn = fmaxf(sqrtf(tot), 1e-12f);
    if (t < Dd) {
        float cv = s / cn;
        cent[gid][t] = cv;
        g_B[(size_t)n * Dd + t] = __float2half(cv);
    }
    if (t < Mm) g_rowsum[n * Mm + t] = 0.f;
    GBAR(bar);

    {   // pos: warp w dots its raw row (regs) with fp32 centroid
        const float* cp = &cent[gid][lane * 8];
        float d = x0.x * cp[0] + x0.y * cp[1] + x0.z * cp[2] + x0.w * cp[3]
                + x1.x * cp[4] + x1.y * cp[5] + x1.z * cp[6] + x1.w * cp[7];
#pragma unroll
        for (int off = 16; off > 0; off >>= 1) d += __shfl_xor_sync(0xffffffffu, d, off);
        if (lane == 0) {
            float wabs = fabsf(*wp);
            g_pos[n * Mm + w] = wabs * (d * sc - 1.f);
        }
    }
}

// ---------------------------------------------------------------------------
// Kernel 2: fp16 HMMA (fp16 acc), CTA tile 128x128, 4 warps (2x2), warp tile
// 64x64 (4:1 MMA:LDSM), BK=32, 2-stage cp.async pipeline, 4 CTAs/SM.
// Same per-SM steady state as R9 (16 warps/SM) but half-size tail tile.
// ---------------------------------------------------------------------------
#define BK 32
#define SSTR 40                       // padded row stride (elems); 80B
#define NCHUNK (Dd / BK)              // 8
#define STG (128 * SSTR * 2)          // 10240 B per tile stage

__global__ void __launch_bounds__(128, 4)
gemm_lse_kernel(const float* __restrict__ wp) {
    __shared__ __half smem[2 * 2 * STG / 2];   // 40960 B: [A0 A1 | B0 B1]
    const uint32_t as0 = smem_u32(smem);
    const uint32_t bs0 = as0 + 2 * STG;

    const int tid = threadIdx.x;
    const int wid = tid >> 5, lane = tid & 31;
    const int wm = wid >> 1;          // 0..1  (64-row slice)
    const int wn = wid & 1;           // 0..1  (64-col slice)
    const int r0 = blockIdx.y * 128;
    const int c0 = blockIdx.x * 128;

    const int lrow = tid >> 2;        // 0..31
    const int lquad = tid & 3;

    auto load_chunk = [&](int c, int stg) {
#pragma unroll
        for (int i = 0; i < 4; i++) {
            int row = lrow + i * 32;
            cpa16(as0 + stg * STG + row * (SSTR * 2) + lquad * 16,
                  g_A + (size_t)(r0 + row) * Dd + c * BK + lquad * 8);
            cpa16(bs0 + stg * STG + row * (SSTR * 2) + lquad * 16,
                  g_B + (size_t)(c0 + row) * Dd + c * BK + lquad * 8);
        }
        asm volatile("cp.async.commit_group;" ::: "memory");
    };

    uint32_t acc[4][8][2] = {};       // fp16x2 accumulators

    load_chunk(0, 0);
    load_chunk(1, 1);

#pragma unroll
    for (int c = 0; c < NCHUNK; c++) {
        if (c < 7) asm volatile("cp.async.wait_group 1;" ::: "memory");
        else       asm volatile("cp.async.wait_group 0;" ::: "memory");
        __syncthreads();

        const uint32_t ab = as0 + (c & 1) * STG;
        const uint32_t bb = bs0 + (c & 1) * STG;
#pragma unroll
        for (int ks = 0; ks < 2; ks++) {
            const int k0 = ks * 16;
            uint32_t a[4][4];
#pragma unroll
            for (int mt = 0; mt < 4; mt++) {
                int row = wm * 64 + mt * 16 + (lane & 15);
                int col = k0 + (lane >> 4) * 8;
                ldm_x4(a[mt], ab + row * (SSTR * 2) + col * 2);
            }
            uint32_t b[4][4];
#pragma unroll
            for (int ng = 0; ng < 4; ng++) {
                int row = wn * 64 + ng * 16 + (lane & 7) + (lane >> 4) * 8;
                int col = k0 + ((lane >> 3) & 1) * 8;
                ldm_x4(b[ng], bb + row * (SSTR * 2) + col * 2);
            }
#pragma unroll
            for (int mt = 0; mt < 4; mt++)
#pragma unroll
                for (int nt = 0; nt < 8; nt++)
                    mma_f16acc(acc[mt][nt], a[mt],
                               b[nt >> 1][(nt & 1) * 2], b[nt >> 1][(nt & 1) * 2 + 1]);
        }
        __syncthreads();               // stage reuse guard (2-stage)
        if (c + 2 < NCHUNK) load_chunk(c + 2, c & 1);
    }

    // ---- fused epilogue (branch-free): rowsum += exp(|w|*(cos-1)) ----
    const float wabs = fabsf(*wp);
    const float nw = -wabs;
    const int q = lane >> 2, qi = lane & 3;

#pragma unroll
    for (int mt = 0; mt < 4; mt++) {
        const int rowA = r0 + wm * 64 + mt * 16 + q;
        const int rowB = rowA + 8;
        float sA = 0.f, sB = 0.f;
#pragma unroll
        for (int nt = 0; nt < 8; nt++) {
            float2 vA = __half22float2(*(__half2*)&acc[mt][nt][0]);
            float2 vB = __half22float2(*(__half2*)&acc[mt][nt][1]);
            sA += __expf(fmaf(wabs, vA.x, nw)) + __expf(fmaf(wabs, vA.y, nw));
            sB += __expf(fmaf(wabs, vB.x, nw)) + __expf(fmaf(wabs, vB.y, nw));
        }
#pragma unroll
        for (int off = 2; off > 0; off >>= 1) {
            sA += __shfl_xor_sync(0xffffffffu, sA, off);
            sB += __shfl_xor_sync(0xffffffffu, sB, off);
        }
        if (qi == 0) {
            atomicAdd(&g_rowsum[rowA], sA);
            atomicAdd(&g_rowsum[rowB], sB);
        }
    }
}

// ---------------------------------------------------------------------------
// Kernel 3: loss = mean_r( log(rowsum[r]) - pos_t[r] ), 1024 thr, vectorized.
// ---------------------------------------------------------------------------
__global__ void __launch_bounds__(1024) loss_kernel(float* __restrict__ out) {
    __shared__ float red[32];
    const int tid = threadIdx.x;
    float s = 0.f;
#pragma unroll
    for (int i = 0; i < ROWS / 4096; i++) {
        int r4 = tid + i * 1024;
        float4 rs = *(const float4*)&g_rowsum[r4 * 4];
        float4 ps = *(const float4*)&g_pos[r4 * 4];
        s += __logf(rs.x) - ps.x + __logf(rs.y) - ps.y
           + __logf(rs.z) - ps.z + __logf(rs.w) - ps.w;
    }
#pragma unroll
    for (int off = 16; off > 0; off >>= 1) s += __shfl_xor_sync(0xffffffffu, s, off);
    if ((tid & 31) == 0) red[tid >> 5] = s;
    __syncthreads();
    if (tid < 32) {
        float t = red[tid];
#pragma unroll
        for (int off = 16; off > 0; off >>= 1) t += __shfl_xor_sync(0xffffffffu, t, off);
        if (tid == 0) out[0] = t / (float)ROWS;
    }
}

// ---------------------------------------------------------------------------
extern "C" void kernel_launch(void* const* d_in, const int* in_sizes, int n_in,
                              void* d_out, int out_size) {
    const float* emb = (const float*)d_in[0];
    const float* w   = (const float*)d_in[1];
    const float* b   = (const float*)d_in[2];
    (void)b;
    float* out = (float*)d_out;

    prep_kernel<<<Nn / 2, 640>>>(emb, w);
    gemm_lse_kernel<<<dim3(Nn / 128, ROWS / 128), 128>>>(w);
    loss_kernel<<<1, 1024>>>(out);
}

// round 12
// speedup vs baseline: 1.4176x; 1.0421x over previous
#include <cuda_runtime.h>
#include <cuda_fp16.h>
#include <cstdint>

#define Nn 2048
#define Mm 10
#define Dd 256
#define ROWS (Nn * Mm)      // 20480

// ---------------------------------------------------------------------------
// Scratch (device globals; no allocation allowed)
// ---------------------------------------------------------------------------
__device__ __align__(16) __half g_A[(size_t)ROWS * Dd];  // normalized emb, fp16
__device__ __align__(16) __half g_B[(size_t)Nn * Dd];    // normalized centroids, fp16
__device__ float g_rowsum[ROWS];
__device__ float g_pos[ROWS];   // stores t = |w|*(cos-1); shift cancels in lse-pos

__device__ __forceinline__ uint32_t smem_u32(const void* p) {
    uint32_t a;
    asm("{ .reg .u64 t; cvta.to.shared.u64 t, %1; cvt.u32.u64 %0, t; }" : "=r"(a) : "l"(p));
    return a;
}
__device__ __forceinline__ void cpa16(uint32_t dst, const void* src) {
    asm volatile("cp.async.cg.shared.global [%0], [%1], 16;" :: "r"(dst), "l"(src));
}
__device__ __forceinline__ void ldm_x4(uint32_t* r, uint32_t addr) {
    asm volatile("ldmatrix.sync.aligned.m8n8.x4.shared.b16 {%0,%1,%2,%3}, [%4];"
                 : "=r"(r[0]), "=r"(r[1]), "=r"(r[2]), "=r"(r[3]) : "r"(addr));
}
__device__ __forceinline__ void mma_f16acc(uint32_t* c, const uint32_t* a,
                                           uint32_t b0, uint32_t b1) {
    asm volatile(
        "mma.sync.aligned.m16n8k16.row.col.f16.f16.f16.f16 "
        "{%0,%1}, {%2,%3,%4,%5}, {%6,%7}, {%0,%1};"
        : "+r"(c[0]), "+r"(c[1])
        : "r"(a[0]), "r"(a[1]), "r"(a[2]), "r"(a[3]), "r"(b0), "r"(b1));
}
__device__ __forceinline__ float wred32(float v) {
#pragma unroll
    for (int off = 16; off > 0; off >>= 1) v += __shfl_xor_sync(0xffffffffu, v, off);
    return v;
}

// ---------------------------------------------------------------------------
// Kernel 1: prep, warp-per-speaker, registers only (no smem, no barriers).
// Each lane holds 8 components of all 10 rows. Produces fp16 A/B, fp32-exact
// pos = |w|*(cos-1), zeroes rowsum.
// ---------------------------------------------------------------------------
__global__ void __launch_bounds__(256) prep_kernel(const float* __restrict__ emb,
                                                   const float* __restrict__ wp) {
    const int warp = threadIdx.x >> 5, lane = threadIdx.x & 31;
    const int n = blockIdx.x * 8 + warp;

    float4 x[Mm][2];
    const float* src = emb + (size_t)n * Mm * Dd + lane * 8;
#pragma unroll
    for (int m = 0; m < Mm; m++) {
        x[m][0] = *(const float4*)(src + m * Dd);
        x[m][1] = *(const float4*)(src + m * Dd + 4);
    }

    // per-row inverse norms
    float sc[Mm];
#pragma unroll
    for (int m = 0; m < Mm; m++) {
        float4 a = x[m][0], b = x[m][1];
        float ss = a.x * a.x + a.y * a.y + a.z * a.z + a.w * a.w
                 + b.x * b.x + b.y * b.y + b.z * b.z + b.w * b.w;
        ss = wred32(ss);
        sc[m] = 1.f / fmaxf(sqrtf(ss), 1e-12f);
    }

    // store normalized rows as fp16
#pragma unroll
    for (int m = 0; m < Mm; m++) {
        float4 a = x[m][0], b = x[m][1];
        float s = sc[m];
        __half2 p0 = __floats2half2_rn(a.x * s, a.y * s);
        __half2 p1 = __floats2half2_rn(a.z * s, a.w * s);
        __half2 p2 = __floats2half2_rn(b.x * s, b.y * s);
        __half2 p3 = __floats2half2_rn(b.z * s, b.w * s);
        uint4 v{*(uint32_t*)&p0, *(uint32_t*)&p1, *(uint32_t*)&p2, *(uint32_t*)&p3};
        *(uint4*)(g_A + (size_t)(n * Mm + m) * Dd + lane * 8) = v;
    }

    // centroid = l2norm(sum of raw rows) (scale-invariant)
    float s0 = 0, s1 = 0, s2 = 0, s3 = 0, s4 = 0, s5 = 0, s6 = 0, s7 = 0;
#pragma unroll
    for (int m = 0; m < Mm; m++) {
        s0 += x[m][0].x; s1 += x[m][0].y; s2 += x[m][0].z; s3 += x[m][0].w;
        s4 += x[m][1].x; s5 += x[m][1].y; s6 += x[m][1].z; s7 += x[m][1].w;
    }
    float cs = wred32(s0 * s0 + s1 * s1 + s2 * s2 + s3 * s3
                    + s4 * s4 + s5 * s5 + s6 * s6 + s7 * s7);
    float cinv = 1.f / fmaxf(sqrtf(cs), 1e-12f);
    {
        __half2 p0 = __floats2half2_rn(s0 * cinv, s1 * cinv);
        __half2 p1 = __floats2half2_rn(s2 * cinv, s3 * cinv);
        __half2 p2 = __floats2half2_rn(s4 * cinv, s5 * cinv);
        __half2 p3 = __floats2half2_rn(s6 * cinv, s7 * cinv);
        uint4 v{*(uint32_t*)&p0, *(uint32_t*)&p1, *(uint32_t*)&p2, *(uint32_t*)&p3};
        *(uint4*)(g_B + (size_t)n * Dd + lane * 8) = v;
    }

    // pos_m = |w| * (sc[m] * cinv * dot(x_m, rawsum) - 1), fp32 exact
    const float wabs = fabsf(*wp);
#pragma unroll
    for (int m = 0; m < Mm; m++) {
        float4 a = x[m][0], b = x[m][1];
        float d = a.x * s0 + a.y * s1 + a.z * s2 + a.w * s3
                + b.x * s4 + b.y * s5 + b.z * s6 + b.w * s7;
        d = wred32(d);
        if (lane == m) ;                 // (keep all lanes; write below from lane 0)
        if (lane == 0) g_pos[n * Mm + m] = wabs * (d * sc[m] * cinv - 1.f);
    }
    if (lane < Mm) g_rowsum[n * Mm + lane] = 0.f;
}

// ---------------------------------------------------------------------------
// Kernel 2: fp16 HMMA (fp16 acc), CTA tile 128x128, 4 warps (2x2), warp tile
// 64x64 (4:1 MMA:LDSM), BK=32, 2-stage cp.async pipeline, 4 CTAs/SM.
// ---------------------------------------------------------------------------
#define BK 32
#define SSTR 40                       // padded row stride (elems); 80B
#define NCHUNK (Dd / BK)              // 8
#define STG (128 * SSTR * 2)          // 10240 B per tile stage

__global__ void __launch_bounds__(128, 4)
gemm_lse_kernel(const float* __restrict__ wp) {
    __shared__ __half smem[2 * 2 * STG / 2];   // 40960 B: [A0 A1 | B0 B1]
    const uint32_t as0 = smem_u32(smem);
    const uint32_t bs0 = as0 + 2 * STG;

    const int tid = threadIdx.x;
    const int wid = tid >> 5, lane = tid & 31;
    const int wm = wid >> 1;          // 0..1  (64-row slice)
    const int wn = wid & 1;           // 0..1  (64-col slice)
    const int r0 = blockIdx.y * 128;
    const int c0 = blockIdx.x * 128;

    const int lrow = tid >> 2;        // 0..31
    const int lquad = tid & 3;

    auto load_chunk = [&](int c, int stg) {
#pragma unroll
        for (int i = 0; i < 4; i++) {
            int row = lrow + i * 32;
            cpa16(as0 + stg * STG + row * (SSTR * 2) + lquad * 16,
                  g_A + (size_t)(r0 + row) * Dd + c * BK + lquad * 8);
            cpa16(bs0 + stg * STG + row * (SSTR * 2) + lquad * 16,
                  g_B + (size_t)(c0 + row) * Dd + c * BK + lquad * 8);
        }
        asm volatile("cp.async.commit_group;" ::: "memory");
    };

    uint32_t acc[4][8][2] = {};       // fp16x2 accumulators

    load_chunk(0, 0);
    load_chunk(1, 1);

#pragma unroll
    for (int c = 0; c < NCHUNK; c++) {
        if (c < 7) asm volatile("cp.async.wait_group 1;" ::: "memory");
        else       asm volatile("cp.async.wait_group 0;" ::: "memory");
        __syncthreads();

        const uint32_t ab = as0 + (c & 1) * STG;
        const uint32_t bb = bs0 + (c & 1) * STG;
#pragma unroll
        for (int ks = 0; ks < 2; ks++) {
            const int k0 = ks * 16;
            uint32_t a[4][4];
#pragma unroll
            for (int mt = 0; mt < 4; mt++) {
                int row = wm * 64 + mt * 16 + (lane & 15);
                int col = k0 + (lane >> 4) * 8;
                ldm_x4(a[mt], ab + row * (SSTR * 2) + col * 2);
            }
            uint32_t b[4][4];
#pragma unroll
            for (int ng = 0; ng < 4; ng++) {
                int row = wn * 64 + ng * 16 + (lane & 7) + (lane >> 4) * 8;
                int col = k0 + ((lane >> 3) & 1) * 8;
                ldm_x4(b[ng], bb + row * (SSTR * 2) + col * 2);
            }
#pragma unroll
            for (int mt = 0; mt < 4; mt++)
#pragma unroll
                for (int nt = 0; nt < 8; nt++)
                    mma_f16acc(acc[mt][nt], a[mt],
                               b[nt >> 1][(nt & 1) * 2], b[nt >> 1][(nt & 1) * 2 + 1]);
        }
        __syncthreads();               // stage reuse guard (2-stage)
        if (c + 2 < NCHUNK) load_chunk(c + 2, c & 1);
    }

    // ---- fused epilogue (branch-free): rowsum += exp(|w|*(cos-1)) ----
    const float wabs = fabsf(*wp);
    const float nw = -wabs;
    const int q = lane >> 2, qi = lane & 3;

#pragma unroll
    for (int mt = 0; mt < 4; mt++) {
        const int rowA = r0 + wm * 64 + mt * 16 + q;
        const int rowB = rowA + 8;
        float sA = 0.f, sB = 0.f;
#pragma unroll
        for (int nt = 0; nt < 8; nt++) {
            float2 vA = __half22float2(*(__half2*)&acc[mt][nt][0]);
            float2 vB = __half22float2(*(__half2*)&acc[mt][nt][1]);
            sA += __expf(fmaf(wabs, vA.x, nw)) + __expf(fmaf(wabs, vA.y, nw));
            sB += __expf(fmaf(wabs, vB.x, nw)) + __expf(fmaf(wabs, vB.y, nw));
        }
#pragma unroll
        for (int off = 2; off > 0; off >>= 1) {
            sA += __shfl_xor_sync(0xffffffffu, sA, off);
            sB += __shfl_xor_sync(0xffffffffu, sB, off);
        }
        if (qi == 0) {
            atomicAdd(&g_rowsum[rowA], sA);
            atomicAdd(&g_rowsum[rowB], sB);
        }
    }
}

// ---------------------------------------------------------------------------
// Kernel 3: loss = mean_r( log(rowsum[r]) - pos_t[r] ), 1024 thr, vectorized.
// ---------------------------------------------------------------------------
__global__ void __launch_bounds__(1024) loss_kernel(float* __restrict__ out) {
    __shared__ float red[32];
    const int tid = threadIdx.x;
    float s = 0.f;
#pragma unroll
    for (int i = 0; i < ROWS / 4096; i++) {
        int r4 = tid + i * 1024;
        float4 rs = *(const float4*)&g_rowsum[r4 * 4];
        float4 ps = *(const float4*)&g_pos[r4 * 4];
        s += __logf(rs.x) - ps.x + __logf(rs.y) - ps.y
           + __logf(rs.z) - ps.z + __logf(rs.w) - ps.w;
    }
#pragma unroll
    for (int off = 16; off > 0; off >>= 1) s += __shfl_xor_sync(0xffffffffu, s, off);
    if ((tid & 31) == 0) red[tid >> 5] = s;
    __syncthreads();
    if (tid < 32) {
        float t = red[tid];
#pragma unroll
        for (int off = 16; off > 0; off >>= 1) t += __shfl_xor_sync(0xffffffffu, t, off);
        if (tid == 0) out[0] = t / (float)ROWS;
    }
}

// ---------------------------------------------------------------------------
extern "C" void kernel_launch(void* const* d_in, const int* in_sizes, int n_in,
                              void* d_out, int out_size) {
    const float* emb = (const float*)d_in[0];
    const float* w   = (const float*)d_in[1];
    const float* b   = (const float*)d_in[2];
    (void)b;
    float* out = (float*)d_out;

    prep_kernel<<<Nn / 8, 256>>>(emb, w);
    gemm_lse_kernel<<<dim3(Nn / 128, ROWS / 128), 128>>>(w);
    loss_kernel<<<1, 1024>>>(out);
}